// round 1
// baseline (speedup 1.0000x reference)
#include <cuda_runtime.h>
#include <math.h>

// Problem constants
#define E_DIM 1024
#define NHEAD 16
#define HDIM  64
#define BATCH 4
#define SQL   2048
#define SKL   2048

// Scratch (allocation-free rule: __device__ globals)
__device__ float g_Q [BATCH * SQL * E_DIM];   // 33.5 MB
__device__ float g_K [BATCH * SKL * E_DIM];
__device__ float g_V [BATCH * SKL * E_DIM];
__device__ float g_AO[BATCH * SQL * E_DIM];
// Fallback attn buffer in case out_size only covers `output` (1 GB)
__device__ float g_attn_fb[268435456];

// ---------------------------------------------------------------------------
// Batched tiled GEMM, C = alpha * (A @ B^T) [+ bias]
// A: [M,K] row-major (lda), B: [N,K] row-major (ldb), C: [M,N] (ldc)
// Per-z offsets: z -> (b = z/hPer, h = z%hPer); ptr += b*s?b + h*s?h
// Tiles: 64x64 block, BK=16, 256 threads, 4x4 per-thread micro-tile.
// M, N assumed multiples of 64; K multiple of 16 (true for all our shapes).
// ---------------------------------------------------------------------------
__global__ void gemm_nt_kernel(
    const float* __restrict__ A, int lda, long sAb, long sAh,
    const float* __restrict__ Bm, int ldb, long sBb, long sBh,
    float* __restrict__ C, int ldc, long sCb, long sCh,
    const float* __restrict__ bias, int K, float alpha, int hPer)
{
    int bz = blockIdx.z;
    int b = bz / hPer, h = bz - b * hPer;
    A  += (long)b * sAb + (long)h * sAh;
    Bm += (long)b * sBb + (long)h * sBh;
    C  += (long)b * sCb + (long)h * sCh;

    __shared__ float Ast[16][68];  // [k][m]
    __shared__ float Bst[16][68];  // [k][n]

    int tx = threadIdx.x, ty = threadIdx.y;
    int tid = ty * 16 + tx;
    int row0 = blockIdx.y * 64, col0 = blockIdx.x * 64;

    float acc[4][4] = {};

    for (int k0 = 0; k0 < K; k0 += 16) {
#pragma unroll
        for (int u = 0; u < 4; u++) {
            int idx = tid + u * 256;           // 0..1023 over 64x16
            int r = idx >> 4, c = idx & 15;
            Ast[c][r] = A[(long)(row0 + r) * lda + (k0 + c)];
            Bst[c][r] = Bm[(long)(col0 + r) * ldb + (k0 + c)];
        }
        __syncthreads();
#pragma unroll
        for (int kk = 0; kk < 16; kk++) {
            float a[4], bv[4];
#pragma unroll
            for (int i = 0; i < 4; i++) a[i] = Ast[kk][ty * 4 + i];
#pragma unroll
            for (int j = 0; j < 4; j++) bv[j] = Bst[kk][tx * 4 + j];
#pragma unroll
            for (int i = 0; i < 4; i++)
#pragma unroll
                for (int j = 0; j < 4; j++)
                    acc[i][j] += a[i] * bv[j];
        }
        __syncthreads();
    }

#pragma unroll
    for (int i = 0; i < 4; i++) {
        int r = row0 + ty * 4 + i;
#pragma unroll
        for (int j = 0; j < 4; j++) {
            int cl = col0 + tx * 4 + j;
            float v = acc[i][j] * alpha;
            if (bias) v += bias[cl];
            C[(long)r * ldc + cl] = v;
        }
    }
}

// ---------------------------------------------------------------------------
// Batched tiled GEMM, C = A @ B  (B: [K,N] row-major, ldb)
// Same tiling scheme as above.
// ---------------------------------------------------------------------------
__global__ void gemm_nn_kernel(
    const float* __restrict__ A, int lda, long sAb, long sAh,
    const float* __restrict__ Bm, int ldb, long sBb, long sBh,
    float* __restrict__ C, int ldc, long sCb, long sCh,
    int K, int hPer)
{
    int bz = blockIdx.z;
    int b = bz / hPer, h = bz - b * hPer;
    A  += (long)b * sAb + (long)h * sAh;
    Bm += (long)b * sBb + (long)h * sBh;
    C  += (long)b * sCb + (long)h * sCh;

    __shared__ float Ast[16][68];  // [k][m]
    __shared__ float Bs [16][68];  // [k][n]

    int tx = threadIdx.x, ty = threadIdx.y;
    int tid = ty * 16 + tx;
    int row0 = blockIdx.y * 64, col0 = blockIdx.x * 64;

    float acc[4][4] = {};

    for (int k0 = 0; k0 < K; k0 += 16) {
#pragma unroll
        for (int u = 0; u < 4; u++) {
            int idx = tid + u * 256;
            { // A tile 64x16
                int r = idx >> 4, c = idx & 15;
                Ast[c][r] = A[(long)(row0 + r) * lda + (k0 + c)];
            }
            { // B tile 16x64
                int r = idx >> 6, c = idx & 63;
                Bs[r][c] = Bm[(long)(k0 + r) * ldb + (col0 + c)];
            }
        }
        __syncthreads();
#pragma unroll
        for (int kk = 0; kk < 16; kk++) {
            float a[4], bv[4];
#pragma unroll
            for (int i = 0; i < 4; i++) a[i] = Ast[kk][ty * 4 + i];
#pragma unroll
            for (int j = 0; j < 4; j++) bv[j] = Bs[kk][tx * 4 + j];
#pragma unroll
            for (int i = 0; i < 4; i++)
#pragma unroll
                for (int j = 0; j < 4; j++)
                    acc[i][j] += a[i] * bv[j];
        }
        __syncthreads();
    }

#pragma unroll
    for (int i = 0; i < 4; i++) {
        int r = row0 + ty * 4 + i;
#pragma unroll
        for (int j = 0; j < 4; j++) {
            int cl = col0 + tx * 4 + j;
            C[(long)r * ldc + cl] = acc[i][j];
        }
    }
}

// ---------------------------------------------------------------------------
// Row softmax, in place. One block of 256 threads per row of 2048 floats.
// ---------------------------------------------------------------------------
__global__ void softmax_kernel(float* __restrict__ attn)
{
    long row = blockIdx.x;
    float* p = attn + row * (long)SKL;
    int t = threadIdx.x;

    float4* p4 = (float4*)p;
    float4 v0 = p4[t];
    float4 v1 = p4[t + 256];

    __shared__ float sh[8];

    // ---- max reduce ----
    float m = fmaxf(fmaxf(fmaxf(v0.x, v0.y), fmaxf(v0.z, v0.w)),
                    fmaxf(fmaxf(v1.x, v1.y), fmaxf(v1.z, v1.w)));
#pragma unroll
    for (int o = 16; o > 0; o >>= 1)
        m = fmaxf(m, __shfl_xor_sync(0xffffffffu, m, o));
    if ((t & 31) == 0) sh[t >> 5] = m;
    __syncthreads();
    {
        float mm = sh[0];
#pragma unroll
        for (int w = 1; w < 8; w++) mm = fmaxf(mm, sh[w]);
        m = mm;
    }
    __syncthreads();

    // ---- exp + sum ----
    v0.x = __expf(v0.x - m); v0.y = __expf(v0.y - m);
    v0.z = __expf(v0.z - m); v0.w = __expf(v0.w - m);
    v1.x = __expf(v1.x - m); v1.y = __expf(v1.y - m);
    v1.z = __expf(v1.z - m); v1.w = __expf(v1.w - m);

    float s = v0.x + v0.y + v0.z + v0.w + v1.x + v1.y + v1.z + v1.w;
#pragma unroll
    for (int o = 16; o > 0; o >>= 1)
        s += __shfl_xor_sync(0xffffffffu, s, o);
    if ((t & 31) == 0) sh[t >> 5] = s;
    __syncthreads();
    {
        float ss = sh[0];
#pragma unroll
        for (int w = 1; w < 8; w++) ss += sh[w];
        s = ss;
    }

    float r = 1.0f / s;
    v0.x *= r; v0.y *= r; v0.z *= r; v0.w *= r;
    v1.x *= r; v1.y *= r; v1.z *= r; v1.w *= r;

    p4[t]       = v0;
    p4[t + 256] = v1;
}

// ---------------------------------------------------------------------------
extern "C" void kernel_launch(void* const* d_in, const int* in_sizes, int n_in,
                              void* d_out, int out_size)
{
    const float* query = (const float*)d_in[0];
    const float* key   = (const float*)d_in[1];
    const float* value = (const float*)d_in[2];
    const float* Wq    = (const float*)d_in[3];
    const float* bq    = (const float*)d_in[4];
    const float* Wk    = (const float*)d_in[5];
    const float* bk    = (const float*)d_in[6];
    const float* Wv    = (const float*)d_in[7];
    const float* bv    = (const float*)d_in[8];
    const float* Wo    = (const float*)d_in[9];
    const float* bo    = (const float*)d_in[10];
    float* out = (float*)d_out;

    float *Qp, *Kp, *Vp, *AOp, *attn_fb;
    cudaGetSymbolAddress((void**)&Qp,  g_Q);
    cudaGetSymbolAddress((void**)&Kp,  g_K);
    cudaGetSymbolAddress((void**)&Vp,  g_V);
    cudaGetSymbolAddress((void**)&AOp, g_AO);
    cudaGetSymbolAddress((void**)&attn_fb, g_attn_fb);

    const long OUT_ELEMS  = (long)BATCH * SQL * E_DIM;             // 8,388,608
    const long ATTN_ELEMS = (long)BATCH * NHEAD * SQL * (long)SKL; // 268,435,456
    float* attn = ((long)out_size >= OUT_ELEMS + ATTN_ELEMS) ? (out + OUT_ELEMS)
                                                             : attn_fb;

    dim3 blk(16, 16);

    // 1) QKV projections: [8192,1024] @ W^T + b
    {
        dim3 g(E_DIM / 64, (BATCH * SQL) / 64, 1);
        gemm_nt_kernel<<<g, blk>>>(query, E_DIM, 0, 0, Wq, E_DIM, 0, 0,
                                   Qp, E_DIM, 0, 0, bq, E_DIM, 1.0f, 1);
        gemm_nt_kernel<<<g, blk>>>(key,   E_DIM, 0, 0, Wk, E_DIM, 0, 0,
                                   Kp, E_DIM, 0, 0, bk, E_DIM, 1.0f, 1);
        gemm_nt_kernel<<<g, blk>>>(value, E_DIM, 0, 0, Wv, E_DIM, 0, 0,
                                   Vp, E_DIM, 0, 0, bv, E_DIM, 1.0f, 1);
    }

    // 2) scores = (Q_h @ K_h^T) / sqrt(D)  per (b,h);  -> attn buffer
    {
        dim3 g(SKL / 64, SQL / 64, BATCH * NHEAD);
        gemm_nt_kernel<<<g, blk>>>(
            Qp, E_DIM, (long)SQL * E_DIM, (long)HDIM,
            Kp, E_DIM, (long)SKL * E_DIM, (long)HDIM,
            attn, SKL, (long)NHEAD * SQL * SKL, (long)SQL * SKL,
            nullptr, HDIM, 0.125f, NHEAD);
    }

    // 3) softmax rows, in place
    softmax_kernel<<<BATCH * NHEAD * SQL, 256>>>(attn);

    // 4) attn_out_h = attn @ V_h  per (b,h)
    {
        dim3 g(HDIM / 64, SQL / 64, BATCH * NHEAD);
        gemm_nn_kernel<<<g, blk>>>(
            attn, SKL, (long)NHEAD * SQL * SKL, (long)SQL * SKL,
            Vp, E_DIM, (long)SKL * E_DIM, (long)HDIM,
            AOp, E_DIM, (long)SQL * E_DIM, (long)HDIM,
            SKL, NHEAD);
    }

    // 5) output = attn_out @ Wo^T + bo
    {
        dim3 g(E_DIM / 64, (BATCH * SQL) / 64, 1);
        gemm_nt_kernel<<<g, blk>>>(AOp, E_DIM, 0, 0, Wo, E_DIM, 0, 0,
                                   out, E_DIM, 0, 0, bo, E_DIM, 1.0f, 1);
    }
}